// round 1
// baseline (speedup 1.0000x reference)
#include <cuda_runtime.h>
#include <cuda_bf16.h>
#include <math.h>
#include <stdint.h>

// ArcFace loss, single-pass streaming logsumexp with fixed max=32.
// Round 1: HBM-roofline design. 702 MB read once -> expect ~100-130 us.

#define TPB 256

static __device__ float g_rowloss[8192];  // scratch (N=2048; padded)

__device__ __forceinline__ float ex2f(float x) {
    float y;
    asm("ex2.approx.ftz.f32 %0, %1;" : "=f"(y) : "f"(x));
    return y;
}

// exp(32*clip(x,-1,1) - 32) = 2^(K*(c-1)),  K = 32/ln(2)
__device__ __forceinline__ float term(float x, float K) {
    float c = fminf(fmaxf(x, -1.0f), 1.0f);
    return ex2f(fmaf(c, K, -K));
}

__global__ void __launch_bounds__(TPB)
arcface_rowloss_kernel(const float* __restrict__ cosine,
                       const int* __restrict__ targets,
                       int C) {
    const float K     = 46.16624130844682842f;   // 32 / ln 2
    const float COS_M = 0.87758256189037271612f; // cos(0.5)
    const float SIN_M = 0.47942553860420300027f; // sin(0.5)
    const float TH    = -0.87758256189037271612f;// cos(pi-0.5)
    const float MM    = 0.23971276930210150013f; // sin(pi-0.5)*0.5

    const int row = blockIdx.x;
    const int tid = threadIdx.x;
    const float* __restrict__ rp = cosine + (size_t)row * (size_t)C;

    // Peel scalar head to reach 16B alignment for float4 streaming.
    uintptr_t p = (uintptr_t)rp;
    int head = (int)(((16u - (unsigned)(p & 15u)) & 15u) >> 2);
    if (head > C) head = C;
    int nvec = (C - head) >> 2;
    int tailstart = head + (nvec << 2);

    float s0 = 0.0f, s1 = 0.0f, s2 = 0.0f, s3 = 0.0f;

    if (tid < head) s0 += term(rp[tid], K);

    const float4* __restrict__ vp = (const float4*)(rp + head);
    for (int i = tid; i < nvec; i += TPB) {
        float4 v = __ldcs(vp + i);   // streaming, evict-first
        s0 += term(v.x, K);
        s1 += term(v.y, K);
        s2 += term(v.z, K);
        s3 += term(v.w, K);
    }

    int ti = tailstart + tid;
    if (ti < C) s1 += term(rp[ti], K);

    float s = (s0 + s1) + (s2 + s3);

    // Block reduction: warp shuffles + smem across warps.
    __shared__ float warpsums[TPB / 32];
    #pragma unroll
    for (int off = 16; off > 0; off >>= 1)
        s += __shfl_down_sync(0xffffffffu, s, off);
    if ((tid & 31) == 0) warpsums[tid >> 5] = s;
    __syncthreads();

    if (tid == 0) {
        float sum = 0.0f;
        #pragma unroll
        for (int w = 0; w < TPB / 32; w++) sum += warpsums[w];

        // Target-column fixup: replace the cos-term with the phi-term.
        int tgt = targets[row];
        float x = __ldg(rp + tgt);
        float c = fminf(fmaxf(x, -1.0f), 1.0f);
        float sn = sqrtf(fminf(fmaxf(1.0f - c * c, 0.0f), 1.0f));
        float phi = c * COS_M - sn * SIN_M;
        if (!(c > TH)) phi = c - MM;
        sum += ex2f((phi - 1.0f) * K) - ex2f((c - 1.0f) * K);

        // logz - tgt_logit = (32 + ln(sum)) - 32*phi
        g_rowloss[row] = 32.0f + logf(sum) - 32.0f * phi;
    }
}

__global__ void arcface_mean_kernel(float* __restrict__ out, int N) {
    __shared__ float ws[8];
    float s = 0.0f;
    for (int i = threadIdx.x; i < N; i += 256) s += g_rowloss[i];
    #pragma unroll
    for (int off = 16; off > 0; off >>= 1)
        s += __shfl_down_sync(0xffffffffu, s, off);
    if ((threadIdx.x & 31) == 0) ws[threadIdx.x >> 5] = s;
    __syncthreads();
    if (threadIdx.x == 0) {
        float t = 0.0f;
        #pragma unroll
        for (int w = 0; w < 8; w++) t += ws[w];
        out[0] = t / (float)N;
    }
}

extern "C" void kernel_launch(void* const* d_in, const int* in_sizes, int n_in,
                              void* d_out, int out_size) {
    const float* cosine  = (const float*)d_in[0];
    const int*   targets = (const int*)d_in[1];
    int N = in_sizes[1];
    int C = in_sizes[0] / N;

    arcface_rowloss_kernel<<<N, TPB>>>(cosine, targets, C);
    arcface_mean_kernel<<<1, 256>>>((float*)d_out, N);
}

// round 2
// speedup vs baseline: 1.0560x; 1.0560x over previous
#include <cuda_runtime.h>
#include <cuda_bf16.h>
#include <math.h>
#include <stdint.h>

// ArcFace loss, single-pass streaming logsumexp with fixed max=32.
// Round 2: explicit MLP=4 load batching + fused mean (last-block-done).

#define TPB 256

static __device__ float g_rowloss[2048];
static __device__ unsigned int g_done = 0;   // self-resetting; graph-replay safe

__device__ __forceinline__ float ex2f(float x) {
    float y;
    asm("ex2.approx.ftz.f32 %0, %1;" : "=f"(y) : "f"(x));
    return y;
}

// exp(32*clip(x,-1,1) - 32) = 2^(K*(c-1)),  K = 32/ln(2)
__device__ __forceinline__ float term(float x, float K) {
    float c = fminf(fmaxf(x, -1.0f), 1.0f);
    return ex2f(fmaf(c, K, -K));
}

__device__ __forceinline__ void acc4(float4 v, float K,
                                     float& s0, float& s1, float& s2, float& s3) {
    s0 += term(v.x, K);
    s1 += term(v.y, K);
    s2 += term(v.z, K);
    s3 += term(v.w, K);
}

__global__ void __launch_bounds__(TPB)
arcface_fused_kernel(const float* __restrict__ cosine,
                     const int* __restrict__ targets,
                     float* __restrict__ out,
                     int N, int C) {
    const float K     = 46.16624130844682842f;   // 32 / ln 2
    const float COS_M = 0.87758256189037271612f; // cos(0.5)
    const float SIN_M = 0.47942553860420300027f; // sin(0.5)
    const float TH    = -0.87758256189037271612f;// cos(pi-0.5)
    const float MM    = 0.23971276930210150013f; // sin(pi-0.5)*0.5

    const int row = blockIdx.x;
    const int tid = threadIdx.x;
    const float* __restrict__ rp = cosine + (size_t)row * (size_t)C;

    // Peel scalar head to reach 16B alignment for float4 streaming.
    uintptr_t p = (uintptr_t)rp;
    int head = (int)(((16u - (unsigned)(p & 15u)) & 15u) >> 2);
    if (head > C) head = C;
    int nvec = (C - head) >> 2;
    int tailstart = head + (nvec << 2);

    float s0 = 0.0f, s1 = 0.0f, s2 = 0.0f, s3 = 0.0f;

    if (tid < head) s0 += term(rp[tid], K);

    const float4* __restrict__ vp = (const float4*)(rp + head);

    // Main loop: 4 independent LDG.128 batched up front (MLP_p1 = 4).
    int i = tid;
    for (; i + 3 * TPB < nvec; i += 4 * TPB) {
        float4 v0 = __ldcs(vp + i);
        float4 v1 = __ldcs(vp + i + TPB);
        float4 v2 = __ldcs(vp + i + 2 * TPB);
        float4 v3 = __ldcs(vp + i + 3 * TPB);
        acc4(v0, K, s0, s1, s2, s3);
        acc4(v1, K, s0, s1, s2, s3);
        acc4(v2, K, s0, s1, s2, s3);
        acc4(v3, K, s0, s1, s2, s3);
    }
    for (; i < nvec; i += TPB) {
        acc4(__ldcs(vp + i), K, s0, s1, s2, s3);
    }

    int ti = tailstart + tid;
    if (ti < C) s1 += term(rp[ti], K);

    float s = (s0 + s1) + (s2 + s3);

    // Block reduction: warp shuffles + smem across warps.
    __shared__ float warpsums[TPB / 32];
    __shared__ bool  s_last;
    #pragma unroll
    for (int off = 16; off > 0; off >>= 1)
        s += __shfl_down_sync(0xffffffffu, s, off);
    if ((tid & 31) == 0) warpsums[tid >> 5] = s;
    __syncthreads();

    if (tid == 0) {
        float sum = 0.0f;
        #pragma unroll
        for (int w = 0; w < TPB / 32; w++) sum += warpsums[w];

        // Target-column fixup: replace the cos-term with the phi-term.
        int tgt = targets[row];
        float x = __ldg(rp + tgt);
        float c = fminf(fmaxf(x, -1.0f), 1.0f);
        float sn = sqrtf(fminf(fmaxf(1.0f - c * c, 0.0f), 1.0f));
        float phi = c * COS_M - sn * SIN_M;
        if (!(c > TH)) phi = c - MM;
        sum += ex2f((phi - 1.0f) * K) - ex2f((c - 1.0f) * K);

        // rowloss = logz - tgt_logit = (32 + ln(sum)) - 32*phi
        g_rowloss[row] = 32.0f + logf(sum) - 32.0f * phi;

        // Last-block-done protocol (threadfence before atomic; counter
        // self-resets so every graph replay starts from 0).
        __threadfence();
        unsigned int done = atomicAdd(&g_done, 1u);
        s_last = (done == (unsigned int)(gridDim.x - 1));
    }
    __syncthreads();

    if (s_last) {
        // Entire last block reduces the 2048 row losses (deterministic order).
        float m = 0.0f;
        for (int r = tid; r < N; r += TPB) m += g_rowloss[r];
        #pragma unroll
        for (int off = 16; off > 0; off >>= 1)
            m += __shfl_down_sync(0xffffffffu, m, off);
        if ((tid & 31) == 0) warpsums[tid >> 5] = m;
        __syncthreads();
        if (tid == 0) {
            float t = 0.0f;
            #pragma unroll
            for (int w = 0; w < TPB / 32; w++) t += warpsums[w];
            out[0] = t / (float)N;
            g_done = 0;   // reset for next replay
        }
    }
}

extern "C" void kernel_launch(void* const* d_in, const int* in_sizes, int n_in,
                              void* d_out, int out_size) {
    const float* cosine  = (const float*)d_in[0];
    const int*   targets = (const int*)d_in[1];
    int N = in_sizes[1];
    int C = in_sizes[0] / N;

    arcface_fused_kernel<<<N, TPB>>>(cosine, targets, (float*)d_out, N, C);
}

// round 3
// speedup vs baseline: 1.0837x; 1.0262x over previous
#include <cuda_runtime.h>
#include <cuda_bf16.h>
#include <math.h>
#include <stdint.h>

// ArcFace loss, streaming logsumexp with fixed max=32.
// Round 3: 4 segments per row (grid 8192) to kill wave-quantization tail;
// deterministic per-segment partials + fused last-block finalize.

#define TPB  256
#define SEGS 4

static __device__ float g_partial[2048 * SEGS];
static __device__ float g_phi[2048];
static __device__ unsigned int g_done = 0;   // self-resetting; graph-replay safe

__device__ __forceinline__ float ex2f(float x) {
    float y;
    asm("ex2.approx.ftz.f32 %0, %1;" : "=f"(y) : "f"(x));
    return y;
}

// exp(32*clip(x,-1,1) - 32) = 2^(K*(c-1)),  K = 32/ln(2)
__device__ __forceinline__ float term(float x, float K) {
    float c = fminf(fmaxf(x, -1.0f), 1.0f);
    return ex2f(fmaf(c, K, -K));
}

__device__ __forceinline__ void acc4(float4 v, float K,
                                     float& s0, float& s1, float& s2, float& s3) {
    s0 += term(v.x, K);
    s1 += term(v.y, K);
    s2 += term(v.z, K);
    s3 += term(v.w, K);
}

__global__ void __launch_bounds__(TPB)
arcface_fused_kernel(const float* __restrict__ cosine,
                     const int* __restrict__ targets,
                     float* __restrict__ out,
                     int N, int C) {
    const float K     = 46.16624130844682842f;   // 32 / ln 2
    const float COS_M = 0.87758256189037271612f; // cos(0.5)
    const float SIN_M = 0.47942553860420300027f; // sin(0.5)
    const float TH    = -0.87758256189037271612f;// cos(pi-0.5)
    const float MM    = 0.23971276930210150013f; // sin(pi-0.5)*0.5

    const int bid = blockIdx.x;
    const int row = bid >> 2;          // SEGS = 4
    const int seg = bid & 3;
    const int tid = threadIdx.x;

    const float* __restrict__ rp = cosine + (size_t)row * (size_t)C;

    // Segment [start, end) of this row.
    int start = (int)(((long long)seg * C) >> 2);
    int end   = (int)(((long long)(seg + 1) * C) >> 2);
    const float* __restrict__ sp = rp + start;
    int len = end - start;

    // Peel scalar head to reach 16B alignment for float4 streaming.
    uintptr_t p = (uintptr_t)sp;
    int head = (int)(((16u - (unsigned)(p & 15u)) & 15u) >> 2);
    if (head > len) head = len;
    int nvec = (len - head) >> 2;
    int tailstart = head + (nvec << 2);

    float s0 = 0.0f, s1 = 0.0f, s2 = 0.0f, s3 = 0.0f;

    if (tid < head) s0 += term(sp[tid], K);

    const float4* __restrict__ vp = (const float4*)(sp + head);

    // Main loop: 4 independent LDG.128 batched up front (MLP_p1 = 4).
    int i = tid;
    for (; i + 3 * TPB < nvec; i += 4 * TPB) {
        float4 v0 = __ldcs(vp + i);
        float4 v1 = __ldcs(vp + i + TPB);
        float4 v2 = __ldcs(vp + i + 2 * TPB);
        float4 v3 = __ldcs(vp + i + 3 * TPB);
        acc4(v0, K, s0, s1, s2, s3);
        acc4(v1, K, s0, s1, s2, s3);
        acc4(v2, K, s0, s1, s2, s3);
        acc4(v3, K, s0, s1, s2, s3);
    }
    for (; i < nvec; i += TPB) {
        acc4(__ldcs(vp + i), K, s0, s1, s2, s3);
    }

    int ti = tailstart + tid;
    if (ti < len) s1 += term(sp[ti], K);

    float s = (s0 + s1) + (s2 + s3);

    // Block reduction: warp shuffles + smem across warps.
    __shared__ float warpsums[TPB / 32];
    __shared__ bool  s_last;
    #pragma unroll
    for (int off = 16; off > 0; off >>= 1)
        s += __shfl_down_sync(0xffffffffu, s, off);
    if ((tid & 31) == 0) warpsums[tid >> 5] = s;
    __syncthreads();

    if (tid == 0) {
        float sum = 0.0f;
        #pragma unroll
        for (int w = 0; w < TPB / 32; w++) sum += warpsums[w];

        if (seg == 0) {
            // Target-column fixup: swap the cos-term for the phi-term,
            // folded into this segment's partial. Stash phi for finalize.
            int tgt = targets[row];
            float x = __ldg(rp + tgt);
            float c = fminf(fmaxf(x, -1.0f), 1.0f);
            float sn = sqrtf(fminf(fmaxf(1.0f - c * c, 0.0f), 1.0f));
            float phi = c * COS_M - sn * SIN_M;
            if (!(c > TH)) phi = c - MM;
            sum += ex2f((phi - 1.0f) * K) - ex2f((c - 1.0f) * K);
            g_phi[row] = phi;
        }
        g_partial[bid] = sum;

        // Last-block-done protocol.
        __threadfence();
        unsigned int done = atomicAdd(&g_done, 1u);
        s_last = (done == (unsigned int)(gridDim.x - 1));
    }
    __syncthreads();

    if (s_last) {
        __threadfence();  // acquire side: make all partials/phi visible
        float m = 0.0f;
        for (int r = tid; r < N; r += TPB) {
            float t = (g_partial[r * SEGS + 0] + g_partial[r * SEGS + 1]) +
                      (g_partial[r * SEGS + 2] + g_partial[r * SEGS + 3]);
            // rowloss = (32 + ln(sum)) - 32*phi
            m += 32.0f + logf(t) - 32.0f * g_phi[r];
        }
        #pragma unroll
        for (int off = 16; off > 0; off >>= 1)
            m += __shfl_down_sync(0xffffffffu, m, off);
        if ((tid & 31) == 0) warpsums[tid >> 5] = m;
        __syncthreads();
        if (tid == 0) {
            float t = 0.0f;
            #pragma unroll
            for (int w = 0; w < TPB / 32; w++) t += warpsums[w];
            out[0] = t / (float)N;
            g_done = 0;   // reset for next graph replay
        }
    }
}

extern "C" void kernel_launch(void* const* d_in, const int* in_sizes, int n_in,
                              void* d_out, int out_size) {
    const float* cosine  = (const float*)d_in[0];
    const int*   targets = (const int*)d_in[1];
    int N = in_sizes[1];
    int C = in_sizes[0] / N;

    arcface_fused_kernel<<<N * SEGS, TPB>>>(cosine, targets, (float*)d_out, N, C);
}